// round 14
// baseline (speedup 1.0000x reference)
#include <cuda_runtime.h>

// B3-spline à-trous undecimated wavelet transform, J=3, fused single kernel.
// Input  x: (B, 1024, 1024) fp32.  Output: (B, 4, 1024, 1024) = [w1, w2, w3, c3].
//
// Tile 64x64/CTA, cascaded halo 14 (2+4+8). Symmetric taps => conv(reflect) ==
// reflect(conv): one reflect-padded c0 load matches per-level reflect padding.
//
// Structure (R9): convX-first, output fusion only where predicate-free:
//   P1 tpassX c0->t1          P2 tpassY t1->c1
//   P3 tpassX c1->t2 + W1     P4 tpassY t2->c2
//   P5 tpassX c2->t3 + W2     P6 tpassY t3 -> registers -> gmem w3,c3
// P6: RC=64=TILE, HALO=0 => no bounds checks, no STS, coalesced STG.
// W1/W2 ride inside P3/P5 (read-only vs those phases' writes).
//
// R10: kernel is pinned to the L1 wavefront floor (~41.5us at 100% L1; we ran
// 61%). NW 24 -> 28 (896 thr, 2 CTAs/SM = 56 warps, 87.5% occ) to raise L1
// utilization; launch_bounds(896,2) caps regs at 36 (was 38).
//
// Strides: c-planes [x][y] SA=93 (odd: transposed scalar STS + lane-strided
// reads conflict-free); t-planes [y][x] SB=100 (STS.128 phases hit disjoint
// 4-bank groups). Origins c0:-14, c1:-12, c2:-8, c3:0 => all conv offsets 0.
// Buffers: A: c0 -> c2;  B: t1 -> t2 -> t3;  C: c1.

#define IMG_H 1024
#define IMG_W 1024
#define TILE 64
#define SA 93
#define SB 100
#define BUFA (92 * SA)
#define BUFB (92 * SB)
#define SMEM_BYTES ((2 * BUFA + BUFB) * 4)
#define NW 28                    // warps per CTA (896 threads)

#define W0 0.0625f
#define W1f 0.25f
#define W2f 0.375f

__device__ __forceinline__ int refl(int i) {
    if (i < 0) return -i;
    if (i >= IMG_H) return 2 * IMG_H - 2 - i;
    return i;
}

// convX: src = c[x][y] (SA), conv along x, dst = t[y][x] (SB), STS.128 stores.
template <int D, int RR, int RC>
__device__ __forceinline__ void tpassX(const float* __restrict__ src,
                                       float* __restrict__ dst,
                                       int warp, int lane) {
    constexpr int GC = (RC + 31) / 32;
    constexpr int GR = RR / 8;
    constexpr int L = 8 + 4 * D;
    for (int g = warp; g < GC * GR; g += NW) {
        int c  = (g % GC) * 32 + lane;    // y
        int r0 = (g / GC) * 8;            // x base
        if (c >= RC) continue;
        float v[L];
#pragma unroll
        for (int i = 0; i < L; i++) v[i] = src[(r0 + i) * SA + c];
        float o[8];
#pragma unroll
        for (int i = 0; i < 8; i++)
            o[i] = W0 * (v[i] + v[i + 4 * D]) + W1f * (v[i + D] + v[i + 3 * D]) +
                   W2f * v[i + 2 * D];
        float4* dp = (float4*)(dst + c * SB + r0);   // 16B-aligned
        dp[0] = make_float4(o[0], o[1], o[2], o[3]);
        dp[1] = make_float4(o[4], o[5], o[6], o[7]);
    }
}

// convY (mid levels): src = t[y][x] (SB), conv along y, dst = c_j[x][y] (SA).
template <int D, int RR, int RC>
__device__ __forceinline__ void tpassY(const float* __restrict__ src,
                                       float* __restrict__ dst,
                                       int warp, int lane) {
    constexpr int GC = (RC + 31) / 32;
    constexpr int GR = RR / 8;
    constexpr int L = 8 + 4 * D;
    for (int g = warp; g < GC * GR; g += NW) {
        int c  = (g % GC) * 32 + lane;    // x
        int r0 = (g / GC) * 8;            // y base
        if (c >= RC) continue;
        float v[L];
#pragma unroll
        for (int i = 0; i < L; i++) v[i] = src[(r0 + i) * SB + c];
#pragma unroll
        for (int i = 0; i < 8; i++)
            dst[c * SA + r0 + i] =
                W0 * (v[i] + v[i + 4 * D]) + W1f * (v[i + D] + v[i + 3 * D]) +
                W2f * v[i + 2 * D];
    }
}

// convY final (d=4, 64x64): predicate-free; c3 never touches smem.
__device__ __forceinline__ void tpassY_last(const float* __restrict__ src,  // t3 (SB)
                                            const float* __restrict__ prev, // c2 (SA)
                                            float* __restrict__ gw,
                                            float* __restrict__ gc,
                                            int warp, int lane) {
    constexpr int GC = 2, GR = 8, L = 24;
    for (int g = warp; g < GC * GR; g += NW) {
        int c  = (g % GC) * 32 + lane;    // x: 0..63
        int r0 = (g / GC) * 8;            // y base
        float v[L];
#pragma unroll
        for (int i = 0; i < L; i++) v[i] = src[(r0 + i) * SB + c];
        const float* pp = prev + (c + 8) * SA + (r0 + 8);
        float* gwp = gw + (size_t)r0 * IMG_W + c;
        float* gcp = gc + (size_t)r0 * IMG_W + c;
#pragma unroll
        for (int i = 0; i < 8; i++) {
            float o = W0 * (v[i] + v[i + 16]) + W1f * (v[i + 4] + v[i + 12]) +
                      W2f * v[i + 8];
            gwp[(size_t)i * IMG_W] = pp[i] - o;
            gcp[(size_t)i * IMG_W] = o;
        }
    }
}

// Balanced writeout on [x][y] planes: w = prev - cur, coalesced gmem rows.
// 896 threads cover 14 rows x 64 cols; rows strided by 14 over 64.
template <int HP, int HC>
__device__ __forceinline__ void writeout(const float* __restrict__ prev,
                                         const float* __restrict__ cur,
                                         float* __restrict__ gw, int tid) {
    int yt = tid >> 6;           // 0..13
    int xt = tid & 63;
    const float* pp = prev + (HP + xt) * SA + (HP + yt);
    const float* cp = cur + (HC + xt) * SA + (HC + yt);
    float* gwp = gw + (size_t)yt * IMG_W + xt;
#pragma unroll
    for (int i = 0; i < 5; i++) {
        int y = yt + i * 14;
        if (y < TILE) gwp[(size_t)i * 14 * IMG_W] = pp[i * 14] - cp[i * 14];
    }
}

__global__ __launch_bounds__(32 * NW, 2)
void uwt_kernel(const float* __restrict__ x, float* __restrict__ out) {
    extern __shared__ float sm[];
    float* A  = sm;                      // c0[x][y] -> c2[x][y]  (SA)
    float* Bb = sm + BUFA;               // t1 -> t2 -> t3 [y][x] (SB)
    float* Cc = sm + BUFA + BUFB;        // c1[x][y]              (SA)

    const int tid  = threadIdx.x;
    const int lane = tid & 31;
    const int warp = tid >> 5;
    const int tx0  = blockIdx.x * TILE;
    const int ty0  = blockIdx.y * TILE;
    const int b    = blockIdx.z;

    const float* xb = x + (size_t)b * IMG_H * IMG_W;

    // Load c0 region 92x92 (origin -14, reflect) transposed into A[x][y].
    for (int yl = warp; yl < 92; yl += NW) {
        const float* row = xb + (size_t)refl(ty0 - 14 + yl) * IMG_W;
#pragma unroll
        for (int cg = 0; cg < 3; cg++) {
            int xl = cg * 32 + lane;
            if (xl < 92) A[xl * SA + yl] = row[refl(tx0 - 14 + xl)];
        }
    }
    __syncthreads();

    float* base = out + (size_t)b * 4 * IMG_H * IMG_W;
    float* w1p = base + 0 * (size_t)IMG_H * IMG_W + (size_t)ty0 * IMG_W + tx0;
    float* w2p = base + 1 * (size_t)IMG_H * IMG_W + (size_t)ty0 * IMG_W + tx0;
    float* w3p = base + 2 * (size_t)IMG_H * IMG_W + (size_t)ty0 * IMG_W + tx0;
    float* c3p = base + 3 * (size_t)IMG_H * IMG_W + (size_t)ty0 * IMG_W + tx0;

    // P1: t1 = convX(c0): A -> B   (x 92->88, y 92)
    tpassX<1, 88, 92>(A, Bb, warp, lane);
    __syncthreads();
    // P2: c1 = convY(t1): B -> C   (88x88, origin -12)
    tpassY<1, 88, 88>(Bb, Cc, warp, lane);
    __syncthreads();
    // P3: t2 = convX(c1): C -> B  (+ w1 = c0 - c1; reads A,C only)
    tpassX<2, 80, 88>(Cc, Bb, warp, lane);
    writeout<14, 12>(A, Cc, w1p, tid);
    __syncthreads();
    // P4: c2 = convY(t2): B -> A   (80x80, origin -8; c0 dead)
    tpassY<2, 80, 80>(Bb, A, warp, lane);
    __syncthreads();
    // P5: t3 = convX(c2): A -> B  (+ w2 = c1 - c2; reads C,A only)
    tpassX<4, 64, 80>(A, Bb, warp, lane);
    writeout<12, 8>(Cc, A, w2p, tid);
    __syncthreads();
    // P6: c3 = convY(t3) in registers; w3 = c2 - c3 and c3 straight to gmem.
    tpassY_last(Bb, A, w3p, c3p, warp, lane);
}

extern "C" void kernel_launch(void* const* d_in, const int* in_sizes, int n_in,
                              void* d_out, int out_size) {
    const float* x = (const float*)d_in[0];
    float* out = (float*)d_out;
    int batch = in_sizes[0] / (IMG_H * IMG_W);

    cudaFuncSetAttribute(uwt_kernel, cudaFuncAttributeMaxDynamicSharedMemorySize,
                         SMEM_BYTES);

    dim3 grid(IMG_W / TILE, IMG_H / TILE, batch);
    dim3 block(32 * NW);
    uwt_kernel<<<grid, block, SMEM_BYTES>>>(x, out);
}